// round 6
// baseline (speedup 1.0000x reference)
#include <cuda_runtime.h>
#include <math.h>

#define N_COMBOS   64
#define N_STRUCTS  512
#define HID        1024
#define BATCH      2048
#define NITERS     60
#define POW_ITERS  30
#define RB         8

#define MAX_NNZ_G   32768
#define RSTEP_CAP   1536
#define CSTEP_CAP   1792

// ---------------- device scratch ----------------
__device__ float g_A1[BATCH * HID];
__device__ float g_A2[BATCH * HID];
__device__ float g_Z [BATCH * N_STRUCTS];
__device__ float g_tau;

__device__ int            g_row_ptr[N_COMBOS + 1];
__device__ unsigned short g_row_idx[MAX_NNZ_G];
__device__ int            g_col_ptr[N_STRUCTS + 1];
__device__ unsigned char  g_col_idx[MAX_NNZ_G];

__device__ unsigned short g_row_ord[N_COMBOS * 128];   // per-row class-sorted col lists
__device__ unsigned char  g_col_ord[N_STRUCTS * 32];   // per-col class-sorted row lists
__device__ int            g_ccnt[N_STRUCTS];           // packed per-class counts (8b each)

__device__ int            g_rp[N_COMBOS + 1];          // row ELL step offsets
__device__ unsigned short g_ridx[RSTEP_CAP * 4];       // 4 col indices per step, sentinel 512
__device__ int            g_cgo[129];                  // col-group step offsets
__device__ unsigned char  g_cge[CSTEP_CAP * 4];        // 4 row indices per step, sentinel 64

// ---------------- prep ----------------
__global__ __launch_bounds__(512) void prep_kernel(const float* __restrict__ S) {
    __shared__ int cnt[N_STRUCTS];
    __shared__ int sh_steps[N_COMBOS];
    __shared__ int sh_L[128];
    int tid = threadIdx.x;

    // CSR rows (64)
    if (tid < N_COMBOS) {
        int c = 0;
        for (int j = 0; j < N_STRUCTS; j++) if (S[tid * N_STRUCTS + j] != 0.f) c++;
        cnt[tid] = c;
    }
    __syncthreads();
    if (tid == 0) {
        int acc = 0;
        for (int i = 0; i < N_COMBOS; i++) { g_row_ptr[i] = acc; acc += cnt[i]; }
        g_row_ptr[N_COMBOS] = acc;
    }
    __syncthreads();
    if (tid < N_COMBOS) {
        int p = g_row_ptr[tid];
        for (int j = 0; j < N_STRUCTS; j++)
            if (S[tid * N_STRUCTS + j] != 0.f) g_row_idx[p++] = (unsigned short)j;
    }
    __syncthreads();

    // CSC cols (512)
    {
        int c = 0;
        for (int i = 0; i < N_COMBOS; i++) if (S[i * N_STRUCTS + tid] != 0.f) c++;
        cnt[tid] = c;
    }
    __syncthreads();
    if (tid == 0) {
        int acc = 0;
        for (int j = 0; j < N_STRUCTS; j++) { g_col_ptr[j] = acc; acc += cnt[j]; }
        g_col_ptr[N_STRUCTS] = acc;
    }
    __syncthreads();
    {
        int p = g_col_ptr[tid];
        for (int i = 0; i < N_COMBOS; i++)
            if (S[i * N_STRUCTS + tid] != 0.f) g_col_idx[p++] = (unsigned char)i;
    }
    __syncthreads();

    // ---- row pass A: counting-sort each row's col list by (col mod 4) ----
    if (tid < N_COMBOS) {
        int base = g_row_ptr[tid];
        int deg = g_row_ptr[tid + 1] - base; if (deg > 128) deg = 128;
        int c4[4] = {0,0,0,0};
        for (int p = 0; p < deg; p++) c4[g_row_idx[base + p] & 3]++;
        int st[4]; st[0] = 0;
        st[1] = c4[0]; st[2] = st[1] + c4[1]; st[3] = st[2] + c4[2];
        int cur[4] = {st[0], st[1], st[2], st[3]};
        for (int p = 0; p < deg; p++) {
            unsigned short v = g_row_idx[base + p];
            g_row_ord[tid * 128 + cur[v & 3]++] = v;
        }
        int steps = (deg + 3) >> 2;
        #pragma unroll
        for (int c = 0; c < 4; c++) if (c4[c] > steps) steps = c4[c];
        sh_steps[tid] = steps;
    }
    __syncthreads();
    if (tid == 0) {
        int acc = 0;
        for (int i = 0; i < N_COMBOS; i++) {
            g_rp[i] = acc;
            int s = sh_steps[i];
            if (acc + s > RSTEP_CAP) s = RSTEP_CAP - acc;
            acc += s;
        }
        g_rp[N_COMBOS] = acc;
    }
    __syncthreads();
    // ---- row pass B: emit steps with rotating class preference ----
    if (tid < N_COMBOS) {
        int base = g_row_ptr[tid];
        int deg = g_row_ptr[tid + 1] - base; if (deg > 128) deg = 128;
        int c4[4] = {0,0,0,0};
        for (int p = 0; p < deg; p++) c4[g_row_idx[base + p] & 3]++;
        int st[4]; st[0] = 0;
        st[1] = c4[0]; st[2] = st[1] + c4[1]; st[3] = st[2] + c4[2];
        int ptr4[4] = {st[0], st[1], st[2], st[3]};
        int rem[4] = {c4[0], c4[1], c4[2], c4[3]};
        int steps = g_rp[tid + 1] - g_rp[tid];
        int out = g_rp[tid] * 4;
        for (int s = 0; s < steps; s++) {
            #pragma unroll
            for (int k = 0; k < 4; k++) {
                int pref = (s + k) & 3;
                int best = -1;
                #pragma unroll
                for (int c2 = 0; c2 < 4; c2++) {
                    int cc = (pref + c2) & 3;
                    if (best < 0 && rem[cc] > 0) best = cc;
                }
                unsigned short v = 512;
                if (best >= 0) { v = g_row_ord[tid * 128 + ptr4[best]]; ptr4[best]++; rem[best]--; }
                g_ridx[out + s * 4 + k] = v;
            }
        }
    }

    // ---- col pass A: counting-sort each col's row list by (row mod 4) ----
    {
        int j = tid;
        int base = g_col_ptr[j];
        int deg = g_col_ptr[j + 1] - base; if (deg > 32) deg = 32;
        int c4[4] = {0,0,0,0};
        for (int p = 0; p < deg; p++) c4[g_col_idx[base + p] & 3]++;
        int st[4]; st[0] = 0;
        st[1] = c4[0]; st[2] = st[1] + c4[1]; st[3] = st[2] + c4[2];
        int cur[4] = {st[0], st[1], st[2], st[3]};
        for (int p = 0; p < deg; p++) {
            unsigned char v = g_col_idx[base + p];
            g_col_ord[j * 32 + cur[v & 3]++] = v;
        }
        g_ccnt[j] = c4[0] | (c4[1] << 8) | (c4[2] << 16) | (c4[3] << 24);
    }
    __syncthreads();

    // ---- col pass B: group steps ----
    if (tid < 128) {
        int L = 0;
        #pragma unroll
        for (int k = 0; k < 4; k++) {
            int j = 4 * tid + k;
            int d = g_col_ptr[j + 1] - g_col_ptr[j]; if (d > 32) d = 32;
            if (d > L) L = d;
        }
        sh_L[tid] = L;
    }
    __syncthreads();
    if (tid == 0) {
        int acc = 0;
        for (int g = 0; g < 128; g++) {
            g_cgo[g] = acc;
            int s = sh_L[g];
            if (acc + s > CSTEP_CAP) s = CSTEP_CAP - acc;
            acc += s;
        }
        g_cgo[128] = acc;
    }
    __syncthreads();
    // ---- col pass C: fill groups, distinct row-class across the 4 columns ----
    if (tid < 128) {
        int g = tid;
        int rem[4][4], ptr4[4][4];
        #pragma unroll
        for (int k = 0; k < 4; k++) {
            int j = 4 * g + k;
            int packed = g_ccnt[j];
            int acc = 0;
            #pragma unroll
            for (int c = 0; c < 4; c++) {
                int cc = (packed >> (8 * c)) & 255;
                rem[k][c] = cc;
                ptr4[k][c] = acc;
                acc += cc;
            }
        }
        int L = g_cgo[g + 1] - g_cgo[g];
        int out = g_cgo[g] * 4;
        for (int s = 0; s < L; s++) {
            int used = 0;
            #pragma unroll
            for (int k = 0; k < 4; k++) {
                int j = 4 * g + k;
                int best = -1, bv = 0;
                #pragma unroll
                for (int c = 0; c < 4; c++)
                    if (!(used & (1 << c)) && rem[k][c] > bv) { bv = rem[k][c]; best = c; }
                if (best < 0) {
                    bv = 0;
                    #pragma unroll
                    for (int c = 0; c < 4; c++)
                        if (rem[k][c] > bv) { bv = rem[k][c]; best = c; }
                }
                unsigned char v = 64;
                if (best >= 0) {
                    v = g_col_ord[j * 32 + ptr4[k][best]];
                    ptr4[k][best]++; rem[k][best]--;
                    used |= 1 << best;
                }
                g_cge[out + s * 4 + k] = v;
            }
        }
    }
}

// ---------------- power iteration ----------------
__global__ __launch_bounds__(512) void power_kernel() {
    __shared__ float v[N_STRUCTS];
    __shared__ float t[N_COMBOS];
    __shared__ float red[16];
    int tid = threadIdx.x;

    v[tid] = 1.0f / sqrtf((float)N_STRUCTS);
    __syncthreads();

    for (int it = 0; it < POW_ITERS; it++) {
        if (tid < N_COMBOS) {
            float s = 0.f;
            int pe = g_row_ptr[tid + 1];
            for (int p = g_row_ptr[tid]; p < pe; p++) s += v[g_row_idx[p]];
            t[tid] = s;
        }
        __syncthreads();
        float w;
        {
            float s = 0.f;
            int pe = g_col_ptr[tid + 1];
            for (int p = g_col_ptr[tid]; p < pe; p++) s += t[g_col_idx[p]];
            w = s + v[tid];
        }
        float sq = w * w;
        #pragma unroll
        for (int o = 16; o; o >>= 1) sq += __shfl_xor_sync(0xffffffffu, sq, o);
        if ((tid & 31) == 0) red[tid >> 5] = sq;
        __syncthreads();
        float tot = 0.f;
        #pragma unroll
        for (int k = 0; k < 16; k++) tot += red[k];
        v[tid] = w / sqrtf(tot);
        __syncthreads();
    }

    if (tid < N_COMBOS) {
        float s = 0.f;
        int pe = g_row_ptr[tid + 1];
        for (int p = g_row_ptr[tid]; p < pe; p++) s += v[g_row_idx[p]];
        t[tid] = s;
    }
    __syncthreads();
    float w;
    {
        float s = 0.f;
        int pe = g_col_ptr[tid + 1];
        for (int p = g_col_ptr[tid]; p < pe; p++) s += t[g_col_idx[p]];
        w = s + v[tid];
    }
    float dq = v[tid] * w;
    #pragma unroll
    for (int o = 16; o; o >>= 1) dq += __shfl_xor_sync(0xffffffffu, dq, o);
    if ((tid & 31) == 0) red[tid >> 5] = dq;
    __syncthreads();
    if (tid == 0) {
        float tot = 0.f;
        #pragma unroll
        for (int k = 0; k < 16; k++) tot += red[k];
        g_tau = 0.9f / sqrtf(tot);
    }
}

// ---------------- GEMM + bias + relu (64x64x16, 128 threads, 8x4) ----------------
__global__ __launch_bounds__(128) void gemm_bias_relu(
    const float* __restrict__ A, const float* __restrict__ B,
    const float* __restrict__ bias, float* __restrict__ C,
    int M, int N, int K)
{
    const int BK = 16;
    __shared__ __align__(16) float As[BK][64];
    __shared__ __align__(16) float Bs[BK][64];

    const int tid = threadIdx.x;
    const int bm = blockIdx.y * 64;
    const int bn = blockIdx.x * 64;

    const int a_r = tid >> 1, a_c = (tid & 1) * 8;
    const int b_r = tid >> 3, b_c = (tid & 7) * 8;
    const int tx = tid & 15, ty = tid >> 4;

    float acc[8][4];
    #pragma unroll
    for (int i = 0; i < 8; i++)
        #pragma unroll
        for (int j = 0; j < 4; j++) acc[i][j] = 0.f;

    for (int k0 = 0; k0 < K; k0 += BK) {
        float4 av0 = *(const float4*)&A[(size_t)(bm + a_r) * K + k0 + a_c];
        float4 av1 = *(const float4*)&A[(size_t)(bm + a_r) * K + k0 + a_c + 4];
        As[a_c + 0][a_r] = av0.x; As[a_c + 1][a_r] = av0.y;
        As[a_c + 2][a_r] = av0.z; As[a_c + 3][a_r] = av0.w;
        As[a_c + 4][a_r] = av1.x; As[a_c + 5][a_r] = av1.y;
        As[a_c + 6][a_r] = av1.z; As[a_c + 7][a_r] = av1.w;
        float4 bv0 = *(const float4*)&B[(size_t)(k0 + b_r) * N + bn + b_c];
        float4 bv1 = *(const float4*)&B[(size_t)(k0 + b_r) * N + bn + b_c + 4];
        *(float4*)&Bs[b_r][b_c] = bv0;
        *(float4*)&Bs[b_r][b_c + 4] = bv1;
        __syncthreads();

        #pragma unroll
        for (int k = 0; k < BK; k++) {
            float4 a0 = *(const float4*)&As[k][ty * 8];
            float4 a1 = *(const float4*)&As[k][ty * 8 + 4];
            float4 b0 = *(const float4*)&Bs[k][tx * 4];
            float a[8] = {a0.x, a0.y, a0.z, a0.w, a1.x, a1.y, a1.z, a1.w};
            float bb[4] = {b0.x, b0.y, b0.z, b0.w};
            #pragma unroll
            for (int i = 0; i < 8; i++)
                #pragma unroll
                for (int j = 0; j < 4; j++)
                    acc[i][j] = fmaf(a[i], bb[j], acc[i][j]);
        }
        __syncthreads();
    }

    #pragma unroll
    for (int j = 0; j < 4; j++) {
        float bb = bias[bn + tx * 4 + j];
        #pragma unroll
        for (int i = 0; i < 8; i++) {
            float r = acc[i][j] + bb;
            C[(size_t)(bm + ty * 8 + i) * N + bn + tx * 4 + j] = r > 0.f ? r : 0.f;
        }
    }
}

// ---------------- PDHG: batch-minor, 8 batch rows per block ----------------
__global__ __launch_bounds__(256, 2) void pdhg_kernel(
    const float* __restrict__ Zg, const float* __restrict__ Xg,
    float* __restrict__ out)
{
    __shared__ float sx[N_STRUCTS + 1][RB];    // [col][b], col 512 = sentinel 0
    __shared__ float sy1[N_COMBOS + 1][RB];    // [row][b], row 64 = sentinel 0
    __shared__ float sB[N_COMBOS][RB];
    __shared__ float sred[8][8];
    __shared__ int            s_rp[N_COMBOS + 1];
    __shared__ unsigned short s_ridx[RSTEP_CAP * 4];
    __shared__ int            s_cgo[129];
    __shared__ unsigned char  s_cge[CSTEP_CAP * 4];

    const int tid = threadIdx.x;
    const int w = tid >> 5, l = tid & 31;
    const int b = tid & 7, jg = tid >> 3;      // lane's column family: col = jg + 32q
    const int kk = jg & 3;
    const int bl = l & 7, jj4 = l >> 3;
    const int row0 = blockIdx.x * RB;
    const float tau = g_tau, sigma = tau;

    const int nrsteps = g_rp[N_COMBOS];
    const int ncsteps = g_cgo[128];
    for (int p = tid; p <= N_COMBOS; p += 256) s_rp[p] = g_rp[p];
    for (int p = tid; p < nrsteps * 4; p += 256) s_ridx[p] = g_ridx[p];
    for (int p = tid; p <= 128; p += 256) s_cgo[p] = g_cgo[p];
    for (int p = tid; p < ncsteps * 4; p += 256) s_cge[p] = g_cge[p];
    for (int p = tid; p < N_COMBOS * RB; p += 256) {
        int i = p >> 3, bb = p & 7;
        sB[i][bb] = Xg[(row0 + bb) * N_COMBOS + i];
    }
    for (int p = tid; p < (N_COMBOS + 1) * RB; p += 256) ((float*)sy1)[p] = 0.f;
    for (int p = tid; p < (N_STRUCTS + 1) * RB; p += 256) ((float*)sx)[p] = 0.f;

    float Zr[16], xr[16], y2[16], xb[16], dd[16];
    #pragma unroll
    for (int q = 0; q < 16; q++) {
        Zr[q] = Zg[(size_t)(row0 + b) * N_STRUCTS + jg + 32 * q];
        xr[q] = 0.f; y2[q] = 0.f; xb[q] = 0.f;
    }
    __syncthreads();

    for (int it = 0; it < NITERS; it++) {
        // ---- y1: warp w handles rows 8w..8w+7; 4 index streams x 8 batch lanes ----
        #pragma unroll
        for (int r = 0; r < 8; r++) {
            int i = w * 8 + r;
            int s0 = s_rp[i], s1 = s_rp[i + 1];
            float acc = 0.f;
            for (int s = s0; s < s1; s++) {
                int j = s_ridx[s * 4 + jj4];
                acc += sx[j][bl];
            }
            acc += __shfl_down_sync(0xffffffffu, acc, 16);
            acc += __shfl_down_sync(0xffffffffu, acc, 8);
            if (l < 8) {
                float yv = sy1[i][l];
                sy1[i][l] = fmaxf(fmaf(sigma, acc - sB[i][l], yv), 0.f);
            }
        }
        // ---- y2 local ----
        #pragma unroll
        for (int q = 0; q < 16; q++)
            y2[q] = fmaxf(fmaf(-sigma, xb[q], y2[q]), 0.f);
        __syncthreads();

        // ---- g = S^T y1 - y2 ; prox prep ----
        float sumsq = 0.f;
        #pragma unroll
        for (int q = 0; q < 16; q++) {
            int g2 = w + 8 * q;                 // group of columns {4w+32q .. +3}
            int s0 = s_cgo[g2], s1 = s_cgo[g2 + 1];
            float gs = 0.f;
            for (int s = s0; s < s1; s++) {
                int u = s_cge[s * 4 + kk];
                gs += sy1[u][b];
            }
            gs -= y2[q];
            float v = fmaf(-tau, gs, xr[q]);
            float d1 = v + tau - Zr[q];
            dd[q] = d1;
            sumsq = fmaf(d1, d1, sumsq);
        }
        sumsq += __shfl_down_sync(0xffffffffu, sumsq, 16);
        sumsq += __shfl_down_sync(0xffffffffu, sumsq, 8);
        if (l < 8) sred[w][l] = sumsq;
        __syncthreads();

        float tot = 0.f;
        #pragma unroll
        for (int ww = 0; ww < 8; ww++) tot += sred[ww][b];
        float scale = fmaxf(1.f - tau / fmaxf(sqrtf(tot), 1e-12f), 0.f);

        #pragma unroll
        for (int q = 0; q < 16; q++) {
            float xn = fmaf(scale, dd[q], Zr[q]);
            float xbv = 2.f * xn - xr[q];
            xr[q] = xn; xb[q] = xbv;
            sx[jg + 32 * q][b] = xbv;
        }
        __syncthreads();
    }

    #pragma unroll
    for (int q = 0; q < 16; q++)
        out[(size_t)(row0 + b) * N_STRUCTS + jg + 32 * q] = xr[q];
}

// ---------------- launch ----------------
extern "C" void kernel_launch(void* const* d_in, const int* in_sizes, int n_in,
                              void* d_out, int out_size) {
    const float* X  = (const float*)d_in[0];
    const float* W1 = (const float*)d_in[1];
    const float* b1 = (const float*)d_in[2];
    const float* W2 = (const float*)d_in[3];
    const float* b2 = (const float*)d_in[4];
    const float* W3 = (const float*)d_in[5];
    const float* b3 = (const float*)d_in[6];
    const float* S  = (const float*)d_in[7];
    float* out = (float*)d_out;

    float *A1, *A2, *Z;
    cudaGetSymbolAddress((void**)&A1, g_A1);
    cudaGetSymbolAddress((void**)&A2, g_A2);
    cudaGetSymbolAddress((void**)&Z,  g_Z);

    prep_kernel<<<1, 512>>>(S);
    power_kernel<<<1, 512>>>();

    gemm_bias_relu<<<dim3(HID / 64, BATCH / 64), 128>>>(X, W1, b1, A1, BATCH, HID, N_COMBOS);
    gemm_bias_relu<<<dim3(HID / 64, BATCH / 64), 128>>>(A1, W2, b2, A2, BATCH, HID, HID);
    gemm_bias_relu<<<dim3(N_STRUCTS / 64, BATCH / 64), 128>>>(A2, W3, b3, Z, BATCH, N_STRUCTS, HID);

    pdhg_kernel<<<BATCH / RB, 256>>>(Z, X, out);
}

// round 7
// speedup vs baseline: 1.5726x; 1.5726x over previous
#include <cuda_runtime.h>
#include <math.h>

#define N_COMBOS   64
#define N_STRUCTS  512
#define HID        1024
#define BATCH      2048
#define NITERS     60
#define POW_ITERS  30

#define MAX_NNZ_G  32768
#define MAX_LR     96
#define COLCAP     8192
#define ROWS_PER_BLK 8

// ---------------- device scratch ----------------
__device__ float g_A1[BATCH * HID];
__device__ float g_A2[BATCH * HID];
__device__ float g_Z [BATCH * N_STRUCTS];
__device__ float g_tau;

__device__ int            g_row_ptr[N_COMBOS + 1];
__device__ unsigned short g_row_idx[MAX_NNZ_G];
__device__ int            g_col_ptr[N_STRUCTS + 1];
__device__ unsigned char  g_col_idx[MAX_NNZ_G];

__device__ unsigned int   g_ellr[MAX_LR * 32];   // [p][lane]: idx(row=lane) | idx(row=lane+32)<<16 ; sentinel 512
__device__ int            g_len_ellr;
__device__ unsigned short g_cp4[N_STRUCTS + 1];  // padded (mult of 4) CSC offsets
__device__ unsigned char  g_ci4[COLCAP];         // padded CSC col indices; sentinel 64

// ---------------- prep: CSR + CSC + packed ELL/CSC4 (R2's trivial version) ----------------
__global__ __launch_bounds__(512) void prep_kernel(const float* __restrict__ S) {
    __shared__ int cnt[N_STRUCTS];
    int tid = threadIdx.x;

    // rows (64)
    if (tid < N_COMBOS) {
        int c = 0;
        for (int j = 0; j < N_STRUCTS; j++) if (S[tid * N_STRUCTS + j] != 0.f) c++;
        cnt[tid] = c;
    }
    __syncthreads();
    if (tid == 0) {
        int acc = 0;
        for (int i = 0; i < N_COMBOS; i++) { g_row_ptr[i] = acc; acc += cnt[i]; }
        g_row_ptr[N_COMBOS] = acc;
    }
    __syncthreads();
    if (tid < N_COMBOS) {
        int p = g_row_ptr[tid];
        for (int j = 0; j < N_STRUCTS; j++)
            if (S[tid * N_STRUCTS + j] != 0.f) g_row_idx[p++] = (unsigned short)j;
    }
    __syncthreads();

    // cols (512)
    {
        int c = 0;
        for (int i = 0; i < N_COMBOS; i++) if (S[i * N_STRUCTS + tid] != 0.f) c++;
        cnt[tid] = c;
    }
    __syncthreads();
    if (tid == 0) {
        int acc = 0;
        for (int j = 0; j < N_STRUCTS; j++) { g_col_ptr[j] = acc; acc += cnt[j]; }
        g_col_ptr[N_STRUCTS] = acc;
    }
    __syncthreads();
    {
        int p = g_col_ptr[tid];
        for (int i = 0; i < N_COMBOS; i++)
            if (S[i * N_STRUCTS + tid] != 0.f) g_col_idx[p++] = (unsigned char)i;
    }
    __syncthreads();

    // packed row-pair ELL (lanes 0..31)
    if (tid < 32) {
        int ra = g_row_ptr[tid],      la = g_row_ptr[tid + 1]  - ra;
        int rb = g_row_ptr[tid + 32], lb = g_row_ptr[tid + 33] - rb;
        int L = la > lb ? la : lb;
        if (L > MAX_LR) L = MAX_LR;
        for (int p = 0; p < MAX_LR; p++) {
            unsigned a = (p < la) ? g_row_idx[ra + p] : 512u;
            unsigned b = (p < lb) ? g_row_idx[rb + p] : 512u;
            g_ellr[p * 32 + tid] = a | (b << 16);
        }
        #pragma unroll
        for (int o = 16; o; o >>= 1) { int v = __shfl_xor_sync(0xffffffffu, L, o); L = v > L ? v : L; }
        if (tid == 0) g_len_ellr = L;
    }
    // padded CSC offsets (thread 0, 512 iters, cheap)
    if (tid == 0) {
        int acc = 0;
        for (int j = 0; j < N_STRUCTS; j++) {
            g_cp4[j] = (unsigned short)acc;
            int l = g_col_ptr[j + 1] - g_col_ptr[j];
            acc += (l + 3) & ~3;
        }
        g_cp4[N_STRUCTS] = (unsigned short)acc;
    }
    __syncthreads();
    {
        int j = tid;
        int o = g_cp4[j];
        int base = g_col_ptr[j];
        int l = g_col_ptr[j + 1] - base;
        int pl = (l + 3) & ~3;
        for (int p = 0; p < pl && (o + p) < COLCAP; p++)
            g_ci4[o + p] = (p < l) ? g_col_idx[base + p] : (unsigned char)64;
    }
}

// ---------------- power iteration: tau = 0.9 / ||K||_2 ----------------
__global__ __launch_bounds__(512) void power_kernel() {
    __shared__ float v[N_STRUCTS];
    __shared__ float t[N_COMBOS];
    __shared__ float red[16];
    int tid = threadIdx.x;

    v[tid] = 1.0f / sqrtf((float)N_STRUCTS);
    __syncthreads();

    for (int it = 0; it < POW_ITERS; it++) {
        if (tid < N_COMBOS) {
            float s = 0.f;
            int pe = g_row_ptr[tid + 1];
            for (int p = g_row_ptr[tid]; p < pe; p++) s += v[g_row_idx[p]];
            t[tid] = s;
        }
        __syncthreads();
        float w;
        {
            float s = 0.f;
            int pe = g_col_ptr[tid + 1];
            for (int p = g_col_ptr[tid]; p < pe; p++) s += t[g_col_idx[p]];
            w = s + v[tid];
        }
        float sq = w * w;
        #pragma unroll
        for (int o = 16; o; o >>= 1) sq += __shfl_xor_sync(0xffffffffu, sq, o);
        if ((tid & 31) == 0) red[tid >> 5] = sq;
        __syncthreads();
        float tot = 0.f;
        #pragma unroll
        for (int k = 0; k < 16; k++) tot += red[k];
        v[tid] = w / sqrtf(tot);
        __syncthreads();
    }

    if (tid < N_COMBOS) {
        float s = 0.f;
        int pe = g_row_ptr[tid + 1];
        for (int p = g_row_ptr[tid]; p < pe; p++) s += v[g_row_idx[p]];
        t[tid] = s;
    }
    __syncthreads();
    float w;
    {
        float s = 0.f;
        int pe = g_col_ptr[tid + 1];
        for (int p = g_col_ptr[tid]; p < pe; p++) s += t[g_col_idx[p]];
        w = s + v[tid];
    }
    float dq = v[tid] * w;
    #pragma unroll
    for (int o = 16; o; o >>= 1) dq += __shfl_xor_sync(0xffffffffu, dq, o);
    if ((tid & 31) == 0) red[tid >> 5] = dq;
    __syncthreads();
    if (tid == 0) {
        float tot = 0.f;
        #pragma unroll
        for (int k = 0; k < 16; k++) tot += red[k];
        g_tau = 0.9f / sqrtf(tot);
    }
}

// ---------------- GEMM + bias + relu (64x64x16, 128 threads, 8x4) — R4's 132us version ----------------
__global__ __launch_bounds__(128) void gemm_bias_relu(
    const float* __restrict__ A, const float* __restrict__ B,
    const float* __restrict__ bias, float* __restrict__ C,
    int M, int N, int K)
{
    const int BK = 16;
    __shared__ __align__(16) float As[BK][64];
    __shared__ __align__(16) float Bs[BK][64];

    const int tid = threadIdx.x;
    const int bm = blockIdx.y * 64;
    const int bn = blockIdx.x * 64;

    const int a_r = tid >> 1, a_c = (tid & 1) * 8;
    const int b_r = tid >> 3, b_c = (tid & 7) * 8;
    const int tx = tid & 15, ty = tid >> 4;

    float acc[8][4];
    #pragma unroll
    for (int i = 0; i < 8; i++)
        #pragma unroll
        for (int j = 0; j < 4; j++) acc[i][j] = 0.f;

    for (int k0 = 0; k0 < K; k0 += BK) {
        float4 av0 = *(const float4*)&A[(size_t)(bm + a_r) * K + k0 + a_c];
        float4 av1 = *(const float4*)&A[(size_t)(bm + a_r) * K + k0 + a_c + 4];
        As[a_c + 0][a_r] = av0.x; As[a_c + 1][a_r] = av0.y;
        As[a_c + 2][a_r] = av0.z; As[a_c + 3][a_r] = av0.w;
        As[a_c + 4][a_r] = av1.x; As[a_c + 5][a_r] = av1.y;
        As[a_c + 6][a_r] = av1.z; As[a_c + 7][a_r] = av1.w;
        float4 bv0 = *(const float4*)&B[(size_t)(k0 + b_r) * N + bn + b_c];
        float4 bv1 = *(const float4*)&B[(size_t)(k0 + b_r) * N + bn + b_c + 4];
        *(float4*)&Bs[b_r][b_c] = bv0;
        *(float4*)&Bs[b_r][b_c + 4] = bv1;
        __syncthreads();

        #pragma unroll
        for (int k = 0; k < BK; k++) {
            float4 a0 = *(const float4*)&As[k][ty * 8];
            float4 a1 = *(const float4*)&As[k][ty * 8 + 4];
            float4 b0 = *(const float4*)&Bs[k][tx * 4];
            float a[8] = {a0.x, a0.y, a0.z, a0.w, a1.x, a1.y, a1.z, a1.w};
            float bb[4] = {b0.x, b0.y, b0.z, b0.w};
            #pragma unroll
            for (int i = 0; i < 8; i++)
                #pragma unroll
                for (int j = 0; j < 4; j++)
                    acc[i][j] = fmaf(a[i], bb[j], acc[i][j]);
        }
        __syncthreads();
    }

    #pragma unroll
    for (int j = 0; j < 4; j++) {
        float bb = bias[bn + tx * 4 + j];
        #pragma unroll
        for (int i = 0; i < 8; i++) {
            float r = acc[i][j] + bb;
            C[(size_t)(bm + ty * 8 + i) * N + bn + tx * 4 + j] = r > 0.f ? r : 0.f;
        }
    }
}

// ---------------- PDHG: one WARP per batch row, 8 warps per block (R2 + pipelined ELL) ----------------
__global__ __launch_bounds__(256, 2) void pdhg_warp_kernel(
    const float* __restrict__ Zg, const float* __restrict__ Xg,
    float* __restrict__ out)
{
    constexpr int XB = 516;
    __shared__ unsigned int   s_ellr[MAX_LR * 32];
    __shared__ unsigned short s_cp4[N_STRUCTS + 2];
    __shared__ unsigned char  s_ci4[COLCAP];
    __shared__ float          s_xbar[ROWS_PER_BLK][XB];
    __shared__ float          s_y1[ROWS_PER_BLK][68];

    const int tid = threadIdx.x;
    const int w   = tid >> 5;
    const int l   = tid & 31;
    const int row = blockIdx.x * ROWS_PER_BLK + w;
    const float tau = g_tau;
    const float sigma = tau;
    const int LEN = g_len_ellr;

    for (int p = tid; p < LEN * 32; p += 256) s_ellr[p] = g_ellr[p];
    for (int p = tid; p <= N_STRUCTS; p += 256) s_cp4[p] = g_cp4[p];
    {
        int tot = (g_cp4[N_STRUCTS] + 3) & ~3;
        for (int p = tid * 4; p < tot; p += 1024)
            *(unsigned int*)&s_ci4[p] = *(const unsigned int*)&g_ci4[p];
    }

    float* sx  = s_xbar[w];
    float* sy1 = s_y1[w];

    const float B0 = Xg[row * N_COMBOS + l];
    const float B1 = Xg[row * N_COMBOS + l + 32];
    float yy0 = 0.f, yy1 = 0.f;

    float Zr[16], xr[16], y2[16], xb[16], dq[16];
    #pragma unroll
    for (int q = 0; q < 16; q++) {
        int j = q * 32 + l;
        Zr[q] = Zg[(size_t)row * N_STRUCTS + j];
        xr[q] = 0.f; y2[q] = 0.f; xb[q] = 0.f;
        sx[j] = 0.f;
    }
    if (l < XB - 512) sx[512 + l] = 0.f;
    if (l < 4) sy1[64 + l] = 0.f;
    __syncthreads();

    for (int it = 0; it < NITERS; it++) {
        // ---- y1 gather: unroll x2 with index preload (dual accumulators) ----
        float s0a = 0.f, s1a = 0.f, s0b = 0.f, s1b = 0.f;
        int p = 0;
        for (; p + 2 <= LEN; p += 2) {
            unsigned ua = s_ellr[p * 32 + l];
            unsigned ub = s_ellr[(p + 1) * 32 + l];
            float va0 = sx[ua & 0xffffu];
            float va1 = sx[ua >> 16];
            float vb0 = sx[ub & 0xffffu];
            float vb1 = sx[ub >> 16];
            s0a += va0; s1a += va1;
            s0b += vb0; s1b += vb1;
        }
        if (p < LEN) {
            unsigned ua = s_ellr[p * 32 + l];
            s0a += sx[ua & 0xffffu];
            s1a += sx[ua >> 16];
        }
        float s0 = s0a + s0b, s1 = s1a + s1b;
        yy0 = fmaxf(fmaf(sigma, s0 - B0, yy0), 0.f);
        yy1 = fmaxf(fmaf(sigma, s1 - B1, yy1), 0.f);
        sy1[l] = yy0;
        sy1[l + 32] = yy1;

        // ---- y2 = max(y2 - sigma*xbar, 0) ----
        #pragma unroll
        for (int q = 0; q < 16; q++)
            y2[q] = fmaxf(fmaf(-sigma, xb[q], y2[q]), 0.f);
        __syncwarp();

        // ---- g = S^T y1 - y2 ; prox ----
        float sumsq = 0.f;
        #pragma unroll
        for (int q = 0; q < 16; q++) {
            int j = q * 32 + l;
            int o = s_cp4[j], e = s_cp4[j + 1];
            float g = 0.f;
            for (int pp = o; pp < e; pp += 4) {
                unsigned w4 = *(const unsigned int*)&s_ci4[pp];
                g += sy1[w4 & 255u] + sy1[(w4 >> 8) & 255u]
                   + sy1[(w4 >> 16) & 255u] + sy1[w4 >> 24];
            }
            g -= y2[q];
            float v = fmaf(-tau, g, xr[q]);
            float d = v + tau - Zr[q];
            dq[q] = d;
            sumsq = fmaf(d, d, sumsq);
        }
        #pragma unroll
        for (int o = 16; o; o >>= 1) sumsq += __shfl_xor_sync(0xffffffffu, sumsq, o);
        float nrm = sqrtf(sumsq);
        float scale = fmaxf(1.f - tau / fmaxf(nrm, 1e-12f), 0.f);

        #pragma unroll
        for (int q = 0; q < 16; q++) {
            int j = q * 32 + l;
            float xn  = fmaf(scale, dq[q], Zr[q]);
            float xbv = 2.f * xn - xr[q];
            xr[q] = xn;
            xb[q] = xbv;
            sx[j] = xbv;
        }
        __syncwarp();
    }

    #pragma unroll
    for (int q = 0; q < 16; q++)
        out[(size_t)row * N_STRUCTS + q * 32 + l] = xr[q];
}

// ---------------- launch ----------------
extern "C" void kernel_launch(void* const* d_in, const int* in_sizes, int n_in,
                              void* d_out, int out_size) {
    const float* X  = (const float*)d_in[0];
    const float* W1 = (const float*)d_in[1];
    const float* b1 = (const float*)d_in[2];
    const float* W2 = (const float*)d_in[3];
    const float* b2 = (const float*)d_in[4];
    const float* W3 = (const float*)d_in[5];
    const float* b3 = (const float*)d_in[6];
    const float* S  = (const float*)d_in[7];
    float* out = (float*)d_out;

    float *A1, *A2, *Z;
    cudaGetSymbolAddress((void**)&A1, g_A1);
    cudaGetSymbolAddress((void**)&A2, g_A2);
    cudaGetSymbolAddress((void**)&Z,  g_Z);

    prep_kernel<<<1, 512>>>(S);
    power_kernel<<<1, 512>>>();

    gemm_bias_relu<<<dim3(HID / 64, BATCH / 64), 128>>>(X, W1, b1, A1, BATCH, HID, N_COMBOS);
    gemm_bias_relu<<<dim3(HID / 64, BATCH / 64), 128>>>(A1, W2, b2, A2, BATCH, HID, HID);
    gemm_bias_relu<<<dim3(N_STRUCTS / 64, BATCH / 64), 128>>>(A2, W3, b3, Z, BATCH, N_STRUCTS, HID);

    pdhg_warp_kernel<<<BATCH / ROWS_PER_BLK, 256>>>(Z, X, out);
}